// round 14
// baseline (speedup 1.0000x reference)
#include <cuda_runtime.h>
#include <cuda_bf16.h>
#include <cstdint>

#define NN 50000
#define EE 640000

// ---- scratch (static device globals: allocation-free rule) ----
__device__ __align__(16) float g_buf[(size_t)NN * 512];           // [q|x_r] fp32, 102.4MB
__device__ __align__(16) __nv_bfloat16 g_kv[(size_t)NN * 512];    // [k|v] bf16, 51.2MB (L2-resident)
__device__ __align__(16) __nv_bfloat16 g_hhi[(size_t)NN * 256];   // h hi plane
__device__ __align__(16) __nv_bfloat16 g_hlo[(size_t)NN * 256];   // h lo plane
__device__ int g_degcur[2 * NN];
__device__ int g_start[NN + 1];
__device__ int g_esrc[EE];

// ---- warp-level bf16 MMA (m16n8k16, fp32 accum) ----
__device__ __forceinline__ void mma16816(float* c, const uint32_t* a, const uint32_t* b) {
    asm volatile(
        "mma.sync.aligned.m16n8k16.row.col.f32.bf16.bf16.f32 "
        "{%0,%1,%2,%3}, {%4,%5,%6,%7}, {%8,%9}, {%0,%1,%2,%3};\n"
        : "+f"(c[0]), "+f"(c[1]), "+f"(c[2]), "+f"(c[3])
        : "r"(a[0]), "r"(a[1]), "r"(a[2]), "r"(a[3]), "r"(b[0]), "r"(b[1]));
}
#define LDMX4(r, addr)                                                            \
    asm volatile("ldmatrix.sync.aligned.m8n8.x4.shared.b16 {%0,%1,%2,%3}, [%4];"  \
        : "=r"((r)[0]), "=r"((r)[1]), "=r"((r)[2]), "=r"((r)[3]) : "r"(addr))

__device__ __forceinline__ uint32_t smem_u32(const void* p) {
    uint32_t a;
    asm("{ .reg .u64 t; cvta.to.shared.u64 t, %1; cvt.u32.u64 %0, t; }" : "=r"(a) : "l"(p));
    return a;
}
__device__ __forceinline__ void split2(float x0, float x1, __nv_bfloat162& hi, __nv_bfloat162& lo) {
    hi = __floats2bfloat162_rn(x0, x1);
    lo = __floats2bfloat162_rn(x0 - __bfloat162float(__low2bfloat16(hi)),
                               x1 - __bfloat162float(__high2bfloat16(hi)));
}
__device__ __forceinline__ float2 bf2f(uint32_t u) {
    __nv_bfloat162 b = *(__nv_bfloat162*)&u;
    return __bfloat1622float2(b);
}

#define AST 72   // smem row stride in bf16 (conflict-free for ldmatrix)

#define QKV_SMEM_BYTES (4 * 128 * AST * 2 + 512)
#define PROJ_SMEM_BYTES ((2 * 128 * AST + 2 * 64 * AST) * 2 + 256)

// ============================================================================
// Kernel 1 (HMMA + ldmatrix): qkv+skip GEMM. q,x_r -> g_buf fp32; k,v -> g_kv bf16.
// ============================================================================
__global__ __launch_bounds__(256) void gemm_qkvs_mma(
    const float* __restrict__ x,
    const float* __restrict__ Wq, const float* __restrict__ bq,
    const float* __restrict__ Wk, const float* __restrict__ bk,
    const float* __restrict__ Wv, const float* __restrict__ bv,
    const float* __restrict__ Wsk, const float* __restrict__ bsk)
{
    extern __shared__ __nv_bfloat16 sm[];
    __nv_bfloat16* Ahi = sm;
    __nv_bfloat16* Alo = sm + 128 * AST;
    __nv_bfloat16* Whi = sm + 2 * 128 * AST;
    __nv_bfloat16* Wlo = sm + 3 * 128 * AST;
    float* sbias = (float*)(sm + 4 * 128 * AST);

    int t = threadIdx.x;
    int bx = blockIdx.x, by = blockIdx.y;
    int c0 = bx * 128;
    int which = c0 >> 8, dbase = c0 & 255;
    const float* W = (which == 0) ? Wq : (which == 1) ? Wk : (which == 2) ? Wv : Wsk;
    const float* B = (which == 0) ? bq : (which == 1) ? bk : (which == 2) ? bv : bsk;
    int row0 = by * 128;

    if (t < 128) sbias[t] = B[dbase + t];

#pragma unroll
    for (int i = 0; i < 8; i++) {
        int idx = t + i * 256;
        int r = idx >> 4, qd = idx & 15;
        int so = r * AST + qd * 4;
        float4 v = make_float4(0.f, 0.f, 0.f, 0.f);
        int rg = row0 + r;
        if (rg < NN) v = *(const float4*)(x + (size_t)rg * 64 + qd * 4);
        __nv_bfloat162 h0, l0, h1, l1;
        split2(v.x, v.y, h0, l0);
        split2(v.z, v.w, h1, l1);
        *(__nv_bfloat162*)(Ahi + so) = h0;  *(__nv_bfloat162*)(Ahi + so + 2) = h1;
        *(__nv_bfloat162*)(Alo + so) = l0;  *(__nv_bfloat162*)(Alo + so + 2) = l1;
        float4 w4 = *(const float4*)(W + (size_t)(dbase + r) * 64 + qd * 4);
        split2(w4.x, w4.y, h0, l0);
        split2(w4.z, w4.w, h1, l1);
        *(__nv_bfloat162*)(Whi + so) = h0;  *(__nv_bfloat162*)(Whi + so + 2) = h1;
        *(__nv_bfloat162*)(Wlo + so) = l0;  *(__nv_bfloat162*)(Wlo + so + 2) = l1;
    }
    __syncthreads();

    int wid = t >> 5, lane = t & 31;
    int g = lane >> 2, tq = lane & 3;
    int r0 = (wid & 3) * 32;
    int cw = (wid >> 2) * 64;

    int aoff0 = (r0 + (lane & 15)) * AST + (lane >> 4) * 8;
    int aoff1 = (r0 + 16 + (lane & 15)) * AST + (lane >> 4) * 8;
    uint32_t aHi0 = smem_u32(Ahi) + aoff0 * 2, aHi1 = smem_u32(Ahi) + aoff1 * 2;
    uint32_t aLo0 = smem_u32(Alo) + aoff0 * 2, aLo1 = smem_u32(Alo) + aoff1 * 2;
    int bcol = cw + ((lane >> 4) << 3) + (lane & 7);
    int bkh = ((lane >> 3) & 1) * 8;
    uint32_t bHiB = smem_u32(Whi) + (bcol * AST + bkh) * 2;
    uint32_t bLoB = smem_u32(Wlo) + (bcol * AST + bkh) * 2;

    float acc[2][8][4];
#pragma unroll
    for (int mt = 0; mt < 2; mt++)
#pragma unroll
        for (int nt = 0; nt < 8; nt++)
#pragma unroll
            for (int j = 0; j < 4; j++) acc[mt][nt][j] = 0.f;

#pragma unroll
    for (int ks = 0; ks < 4; ks++) {
        uint32_t kbB = ks * 32;
        uint32_t ahi[2][4], alo[2][4];
        LDMX4(ahi[0], aHi0 + kbB);
        LDMX4(ahi[1], aHi1 + kbB);
        LDMX4(alo[0], aLo0 + kbB);
        LDMX4(alo[1], aLo1 + kbB);
#pragma unroll
        for (int ntg = 0; ntg < 4; ntg++) {
            uint32_t cgB = (uint32_t)(ntg * 16 * AST * 2);
            uint32_t bh[4], bl[4];
            LDMX4(bh, bHiB + cgB + kbB);
            LDMX4(bl, bLoB + cgB + kbB);
#pragma unroll
            for (int mt = 0; mt < 2; mt++) {
                mma16816(acc[mt][2 * ntg],     ahi[mt], bh);
                mma16816(acc[mt][2 * ntg + 1], ahi[mt], bh + 2);
                mma16816(acc[mt][2 * ntg],     ahi[mt], bl);
                mma16816(acc[mt][2 * ntg + 1], ahi[mt], bl + 2);
                mma16816(acc[mt][2 * ntg],     alo[mt], bh);
                mma16816(acc[mt][2 * ntg + 1], alo[mt], bh + 2);
            }
        }
    }

    bool isf32 = (which == 0) || (which == 3);
    int f32off = (which == 0) ? 0 : 256;   // q at 0, x_r at 256 in g_buf
    int kvoff  = (which == 1) ? 0 : 256;   // k at 0, v at 256 in g_kv
#pragma unroll
    for (int mt = 0; mt < 2; mt++) {
        int rA = row0 + r0 + mt * 16 + g;
        int rB = rA + 8;
#pragma unroll
        for (int nt = 0; nt < 8; nt++) {
            int lc = cw + nt * 8 + tq * 2;
            float b0 = sbias[lc], b1 = sbias[lc + 1];
            int ch = dbase + lc;
            if (rA < NN) {
                if (isf32)
                    *(float2*)(g_buf + (size_t)rA * 512 + f32off + ch) =
                        make_float2(acc[mt][nt][0] + b0, acc[mt][nt][1] + b1);
                else
                    *(__nv_bfloat162*)(g_kv + (size_t)rA * 512 + kvoff + ch) =
                        __floats2bfloat162_rn(acc[mt][nt][0] + b0, acc[mt][nt][1] + b1);
            }
            if (rB < NN) {
                if (isf32)
                    *(float2*)(g_buf + (size_t)rB * 512 + f32off + ch) =
                        make_float2(acc[mt][nt][2] + b0, acc[mt][nt][3] + b1);
                else
                    *(__nv_bfloat162*)(g_kv + (size_t)rB * 512 + kvoff + ch) =
                        __floats2bfloat162_rn(acc[mt][nt][2] + b0, acc[mt][nt][3] + b1);
            }
        }
    }
}

// ============================================================================
// CSR build: histogram -> exclusive scan (single block) -> scatter
// ============================================================================
__global__ __launch_bounds__(256) void hist_kernel(const int* __restrict__ ei)
{
    int e = blockIdx.x * 256 + threadIdx.x;
    if (e < EE) atomicAdd(&g_degcur[ei[EE + e]], 1);
}

__global__ __launch_bounds__(1024) void scan_kernel()
{
    __shared__ int wsum[32];
    __shared__ int carryS;
    int t = threadIdx.x;
    int lane = t & 31, w = t >> 5;
    if (t == 0) carryS = 0;
    __syncthreads();
    for (int base = 0; base < NN; base += 1024) {
        int i = base + t;
        int v = (i < NN) ? g_degcur[i] : 0;
        int xv = v;
#pragma unroll
        for (int off = 1; off < 32; off <<= 1) {
            int u = __shfl_up_sync(0xffffffffu, xv, off);
            if (lane >= off) xv += u;
        }
        if (lane == 31) wsum[w] = xv;
        __syncthreads();
        if (w == 0) {
            int y = wsum[lane];
#pragma unroll
            for (int off = 1; off < 32; off <<= 1) {
                int u = __shfl_up_sync(0xffffffffu, y, off);
                if (lane >= off) y += u;
            }
            wsum[lane] = y;
        }
        __syncthreads();
        int incl = xv + (w ? wsum[w - 1] : 0);
        int c = carryS;
        if (i < NN) g_start[i] = c + incl - v;
        __syncthreads();
        if (t == 0) carryS = c + wsum[31];
        __syncthreads();
    }
    if (t == 0) g_start[NN] = carryS;
}

__global__ __launch_bounds__(256) void scatter_kernel(const int* __restrict__ ei)
{
    int e = blockIdx.x * 256 + threadIdx.x;
    if (e < EE) {
        int d = ei[EE + e];
        int s = ei[e];
        int pos = g_start[d] + atomicAdd(&g_degcur[NN + d], 1);
        g_esrc[pos] = s;
    }
}

// ============================================================================
// Kernel 3: warp-per-dst attention, 2-edge ILP.
// Half-warp h (lanes 16h..16h+15) processes edge e0+2*it+h; lane covers 16
// channels. Online softmax kept per half (exact), merged once at the end.
// ============================================================================
__global__ __launch_bounds__(256) void attn_kernel(
    const float* __restrict__ Wbeta,
    const float* __restrict__ lng, const float* __restrict__ lnb)
{
    __shared__ float sWb[768];
    __shared__ float sg[256], sb[256];
    int t = threadIdx.x;
    for (int i = t; i < 768; i += 256) sWb[i] = Wbeta[i];
    if (t < 256) { sg[t] = lng[t]; sb[t] = lnb[t]; }
    __syncthreads();

    int warp = t >> 5, lane = t & 31;
    int node = blockIdx.x * 8 + warp;
    if (node >= NN) return;

    int half = lane >> 4;
    int sl = lane & 15;
    int cb = sl * 16;          // 16 channels per lane; head = sl>>2 (4 lanes/head)

    // q: 16 channels fp32, pre-scaled
    const float* qp = g_buf + (size_t)node * 512 + cb;
    float q[16];
#pragma unroll
    for (int i = 0; i < 4; i++) *(float4*)(q + 4 * i) = *(const float4*)(qp + 4 * i);
#pragma unroll
    for (int u = 0; u < 16; u++) q[u] *= 0.125f;   // 1/sqrt(64)

    float m = -1e30f, ssum = 0.f;
    float acc[16];
#pragma unroll
    for (int u = 0; u < 16; u++) acc[u] = 0.f;

    int e0 = g_start[node], e1 = g_start[node + 1];
    for (int eb = e0; eb < e1; eb += 2) {
        int e = eb + half;
        bool valid = (e < e1);
        int src = g_esrc[valid ? e : eb];
        const __nv_bfloat16* kp = g_kv + (size_t)src * 512 + cb;
        uint4 k0 = *(const uint4*)(kp);
        uint4 k1 = *(const uint4*)(kp + 8);
        uint4 v0 = *(const uint4*)(kp + 256);
        uint4 v1 = *(const uint4*)(kp + 264);

        float2 a0 = bf2f(k0.x), a1 = bf2f(k0.y), a2 = bf2f(k0.z), a3 = bf2f(k0.w);
        float2 b0 = bf2f(k1.x), b1 = bf2f(k1.y), b2 = bf2f(k1.z), b3 = bf2f(k1.w);
        float p = q[0]  * a0.x + q[1]  * a0.y + q[2]  * a1.x + q[3]  * a1.y
                + q[4]  * a2.x + q[5]  * a2.y + q[6]  * a3.x + q[7]  * a3.y
                + q[8]  * b0.x + q[9]  * b0.y + q[10] * b1.x + q[11] * b1.y
                + q[12] * b2.x + q[13] * b2.y + q[14] * b3.x + q[15] * b3.y;
        // reduce across the 4 lanes of this head
        p += __shfl_xor_sync(0xffffffffu, p, 1, 4);
        p += __shfl_xor_sync(0xffffffffu, p, 2, 4);

        float pe = valid ? p : -1e30f;
        float mn = fmaxf(m, pe);
        float sc = __expf(m - mn);
        float wgt = valid ? __expf(pe - mn) : 0.f;
        m = mn;
        ssum = ssum * sc + wgt;

        float2 w0 = bf2f(v0.x), w1 = bf2f(v0.y), w2 = bf2f(v0.z), w3 = bf2f(v0.w);
        float2 x0 = bf2f(v1.x), x1 = bf2f(v1.y), x2 = bf2f(v1.z), x3 = bf2f(v1.w);
        acc[0]  = acc[0]  * sc + wgt * w0.x;  acc[1]  = acc[1]  * sc + wgt * w0.y;
        acc[2]  = acc[2]  * sc + wgt * w1.x;  acc[3]  = acc[3]  * sc + wgt * w1.y;
        acc[4]  = acc[4]  * sc + wgt * w2.x;  acc[5]  = acc[5]  * sc + wgt * w2.y;
        acc[6]  = acc[6]  * sc + wgt * w3.x;  acc[7]  = acc[7]  * sc + wgt * w3.y;
        acc[8]  = acc[8]  * sc + wgt * x0.x;  acc[9]  = acc[9]  * sc + wgt * x0.y;
        acc[10] = acc[10] * sc + wgt * x1.x;  acc[11] = acc[11] * sc + wgt * x1.y;
        acc[12] = acc[12] * sc + wgt * x2.x;  acc[13] = acc[13] * sc + wgt * x2.y;
        acc[14] = acc[14] * sc + wgt * x3.x;  acc[15] = acc[15] * sc + wgt * x3.y;
    }

    // merge the two halves (exact two-way online-softmax merge)
    float mo  = __shfl_xor_sync(0xffffffffu, m, 16);
    float sso = __shfl_xor_sync(0xffffffffu, ssum, 16);
    float mT  = fmaxf(m, mo);
    float s0  = __expf(m - mT);
    float s1  = __expf(mo - mT);
    float ssT = ssum * s0 + sso * s1;
    float inv = 1.f / (ssT + 1e-16f);
    float outv[16];
#pragma unroll
    for (int u = 0; u < 16; u++) {
        float ao = __shfl_xor_sync(0xffffffffu, acc[u], 16);
        outv[u] = (acc[u] * s0 + ao * s1) * inv;
    }

    // x_r: 16 channels
    const float* xp = g_buf + (size_t)node * 512 + 256 + cb;
    float xr[16];
#pragma unroll
    for (int i = 0; i < 4; i++) *(float4*)(xr + 4 * i) = *(const float4*)(xp + 4 * i);

    // beta = sigmoid([out, x_r, out-x_r] . Wbeta); halves duplicate -> x0.5
    float part = 0.f;
#pragma unroll
    for (int u = 0; u < 16; u++) {
        int c = cb + u;
        part += outv[u] * sWb[c] + xr[u] * sWb[256 + c] + (outv[u] - xr[u]) * sWb[512 + c];
    }
#pragma unroll
    for (int off = 16; off > 0; off >>= 1)
        part += __shfl_xor_sync(0xffffffffu, part, off);
    part *= 0.5f;
    float beta = 1.f / (1.f + __expf(-part));

    float h[16], sum = 0.f, sq = 0.f;
#pragma unroll
    for (int u = 0; u < 16; u++) {
        h[u] = beta * xr[u] + (1.f - beta) * outv[u];
        sum += h[u];
        sq += h[u] * h[u];
    }
#pragma unroll
    for (int off = 16; off > 0; off >>= 1) {
        sum += __shfl_xor_sync(0xffffffffu, sum, off);
        sq  += __shfl_xor_sync(0xffffffffu, sq, off);
    }
    float mu = sum * (1.f / 512.f);          // halves duplicate -> /512
    float var = sq * (1.f / 512.f) - mu * mu;
    float rstd = rsqrtf(var + 1e-5f);

    if (half == 0) {
        __nv_bfloat162 hh[8], hl[8];
#pragma unroll
        for (int u = 0; u < 8; u++) {
            int c = cb + 2 * u;
            float o0 = (h[2 * u]     - mu) * rstd * sg[c]     + sb[c];
            float o1 = (h[2 * u + 1] - mu) * rstd * sg[c + 1] + sb[c + 1];
            split2(o0, o1, hh[u], hl[u]);
        }
        *(uint4*)(g_hhi + (size_t)node * 256 + cb)     = *(uint4*)hh;
        *(uint4*)(g_hhi + (size_t)node * 256 + cb + 8) = *(uint4*)(hh + 4);
        *(uint4*)(g_hlo + (size_t)node * 256 + cb)     = *(uint4*)hl;
        *(uint4*)(g_hlo + (size_t)node * 256 + cb + 8) = *(uint4*)(hl + 4);
    }
}

// ============================================================================
// Kernel 4 (HMMA + ldmatrix): out[n,64] = relu(h @ Wp^T + bp + x)
// ============================================================================
__global__ __launch_bounds__(256) void gemm_proj_mma(
    const float* __restrict__ x,
    const float* __restrict__ Wp, const float* __restrict__ bp,
    float* __restrict__ out)
{
    extern __shared__ __nv_bfloat16 sm[];
    __nv_bfloat16* Hhi = sm;
    __nv_bfloat16* Hlo = sm + 128 * AST;
    __nv_bfloat16* Phi = sm + 2 * 128 * AST;
    __nv_bfloat16* Plo = sm + 2 * 128 * AST + 64 * AST;
    float* sbias = (float*)(sm + 2 * 128 * AST + 2 * 64 * AST);

    int t = threadIdx.x;
    int row0 = blockIdx.x * 128;
    if (t < 64) sbias[t] = bp[t];

    int wid = t >> 5, lane = t & 31;
    int g = lane >> 2, tq = lane & 3;
    int r0 = wid * 16;

    int aoff = (r0 + (lane & 15)) * AST + (lane >> 4) * 8;
    uint32_t aHiB = smem_u32(Hhi) + aoff * 2;
    uint32_t aLoB = smem_u32(Hlo) + aoff * 2;
    int bcol = ((lane >> 4) << 3) + (lane & 7);
    int bkh = ((lane >> 3) & 1) * 8;
    uint32_t bHiB = smem_u32(Phi) + (bcol * AST + bkh) * 2;
    uint32_t bLoB = smem_u32(Plo) + (bcol * AST + bkh) * 2;

    float acc[8][4];
#pragma unroll
    for (int nt = 0; nt < 8; nt++)
#pragma unroll
        for (int j = 0; j < 4; j++) acc[nt][j] = 0.f;

    for (int kc = 0; kc < 256; kc += 64) {
        __syncthreads();
#pragma unroll
        for (int i = 0; i < 4; i++) {
            int u = t + i * 256;
            int r = u >> 3, qd = u & 7;
            int rg = row0 + r;
            uint4 vh = make_uint4(0, 0, 0, 0), vl = make_uint4(0, 0, 0, 0);
            if (rg < NN) {
                vh = *(const uint4*)(g_hhi + (size_t)rg * 256 + kc + qd * 8);
                vl = *(const uint4*)(g_hlo + (size_t)rg * 256 + kc + qd * 8);
            }
            *(uint4*)(Hhi + r * AST + qd * 8) = vh;
            *(uint4*)(Hlo + r * AST + qd * 8) = vl;
        }
#pragma unroll
        for (int i = 0; i < 4; i++) {
            int u = t + i * 256;
            int r = u >> 4, qd = u & 15;
            float4 w4 = *(const float4*)(Wp + (size_t)r * 256 + kc + qd * 4);
            __nv_bfloat162 h0, l0, h1, l1;
            split2(w4.x, w4.y, h0, l0);
            split2(w4.z, w4.w, h1, l1);
            int so = r * AST + qd * 4;
            *(__nv_bfloat162*)(Phi + so) = h0;  *(__nv_bfloat162*)(Phi + so + 2) = h1;
            *(__nv_bfloat162*)(Plo + so) = l0;  *(__nv_bfloat162*)(Plo + so + 2) = l1;
        }
        __syncthreads();

#pragma unroll
        for (int ks = 0; ks < 4; ks++) {
            uint32_t kbB = ks * 32;
            uint32_t ahi[4], alo[4];
            LDMX4(ahi, aHiB + kbB);
            LDMX4(alo, aLoB + kbB);
#pragma unroll
            for (int ntg = 0; ntg < 4; ntg++) {
                uint32_t cgB = (uint32_t)(ntg * 16 * AST * 2);
                uint32_t bh[4], bl[4];
                LDMX4(bh, bHiB + cgB + kbB);
                LDMX4(bl, bLoB + cgB + kbB);
                mma16816(acc[2 * ntg],     ahi, bh);
                mma16816(acc[2 * ntg + 1], ahi, bh + 2);
                mma16816(acc[2 * ntg],     ahi, bl);
                mma16816(acc[2 * ntg + 1], ahi, bl + 2);
                mma16816(acc[2 * ntg],     alo, bh);
                mma16816(acc[2 * ntg + 1], alo, bh + 2);
            }
        }
    }

    int rA = row0 + r0 + g;
    int rB = rA + 8;
#pragma unroll
    for (int nt = 0; nt < 8; nt++) {
        int lc = nt * 8 + tq * 2;
        float b0 = sbias[lc], b1 = sbias[lc + 1];
        if (rA < NN) {
            float2 xv = *(const float2*)(x + (size_t)rA * 64 + lc);
            *(float2*)(out + (size_t)rA * 64 + lc) =
                make_float2(fmaxf(acc[nt][0] + b0 + xv.x, 0.f), fmaxf(acc[nt][1] + b1 + xv.y, 0.f));
        }
        if (rB < NN) {
            float2 xv = *(const float2*)(x + (size_t)rB * 64 + lc);
            *(float2*)(out + (size_t)rB * 64 + lc) =
                make_float2(fmaxf(acc[nt][2] + b0 + xv.x, 0.f), fmaxf(acc[nt][3] + b1 + xv.y, 0.f));
        }
    }
}

// ============================================================================
// Serial launch order (R11 structure).
// ============================================================================
extern "C" void kernel_launch(void* const* d_in, const int* in_sizes, int n_in,
                              void* d_out, int out_size)
{
    const float* x     = (const float*)d_in[0];
    const int*   ei    = (const int*)d_in[1];
    const float* Wq    = (const float*)d_in[2];
    const float* bq    = (const float*)d_in[3];
    const float* Wk    = (const float*)d_in[4];
    const float* bk    = (const float*)d_in[5];
    const float* Wv    = (const float*)d_in[6];
    const float* bv    = (const float*)d_in[7];
    const float* Wsk   = (const float*)d_in[8];
    const float* bsk   = (const float*)d_in[9];
    const float* Wbeta = (const float*)d_in[10];
    const float* lng   = (const float*)d_in[11];
    const float* lnb   = (const float*)d_in[12];
    const float* Wp    = (const float*)d_in[13];
    const float* bp    = (const float*)d_in[14];
    float* out = (float*)d_out;

    static int attr_set = 0;
    if (!attr_set) {
        cudaFuncSetAttribute(gemm_qkvs_mma,
                             cudaFuncAttributeMaxDynamicSharedMemorySize, QKV_SMEM_BYTES);
        cudaFuncSetAttribute(gemm_proj_mma,
                             cudaFuncAttributeMaxDynamicSharedMemorySize, PROJ_SMEM_BYTES);
        attr_set = 1;
    }

    void* dcp = nullptr;
    cudaGetSymbolAddress(&dcp, g_degcur);
    cudaMemsetAsync(dcp, 0, 2 * NN * sizeof(int));

    hist_kernel<<<2500, 256>>>(ei);
    scan_kernel<<<1, 1024>>>();
    scatter_kernel<<<2500, 256>>>(ei);
    gemm_qkvs_mma<<<dim3(8, 391), 256, QKV_SMEM_BYTES>>>(x, Wq, bq, Wk, bk, Wv, bv, Wsk, bsk);
    attn_kernel<<<6250, 256>>>(Wbeta, lng, lnb);
    gemm_proj_mma<<<391, 256, PROJ_SMEM_BYTES>>>(x, Wp, bp, out);
}

// round 15
// speedup vs baseline: 1.1283x; 1.1283x over previous
#include <cuda_runtime.h>
#include <cuda_bf16.h>
#include <cstdint>

#define NN 50000
#define EE 640000

// ---- scratch (static device globals: allocation-free rule; zero-inited at load,
//      and every launch leaves them zeroed again -> graph replays are identical) ----
__device__ __align__(16) float g_buf[(size_t)NN * 512];           // [q|x_r] fp32, 102.4MB
__device__ __align__(16) __nv_bfloat16 g_kv[(size_t)NN * 512];    // [k|v] bf16, 51.2MB (L2-resident)
__device__ __align__(16) __nv_bfloat16 g_hhi[(size_t)NN * 256];   // h hi plane
__device__ __align__(16) __nv_bfloat16 g_hlo[(size_t)NN * 256];   // h lo plane
__device__ int g_deg[NN];        // degree histogram (zeroed by scan_kernel after use)
__device__ int g_cur[NN];        // scatter cursors (zeroed by attn_kernel after use)
__device__ int g_start[NN + 1];
__device__ int g_esrc[EE];

// ---- warp-level bf16 MMA (m16n8k16, fp32 accum) ----
__device__ __forceinline__ void mma16816(float* c, const uint32_t* a, const uint32_t* b) {
    asm volatile(
        "mma.sync.aligned.m16n8k16.row.col.f32.bf16.bf16.f32 "
        "{%0,%1,%2,%3}, {%4,%5,%6,%7}, {%8,%9}, {%0,%1,%2,%3};\n"
        : "+f"(c[0]), "+f"(c[1]), "+f"(c[2]), "+f"(c[3])
        : "r"(a[0]), "r"(a[1]), "r"(a[2]), "r"(a[3]), "r"(b[0]), "r"(b[1]));
}
#define LDMX4(r, addr)                                                            \
    asm volatile("ldmatrix.sync.aligned.m8n8.x4.shared.b16 {%0,%1,%2,%3}, [%4];"  \
        : "=r"((r)[0]), "=r"((r)[1]), "=r"((r)[2]), "=r"((r)[3]) : "r"(addr))

__device__ __forceinline__ uint32_t smem_u32(const void* p) {
    uint32_t a;
    asm("{ .reg .u64 t; cvta.to.shared.u64 t, %1; cvt.u32.u64 %0, t; }" : "=r"(a) : "l"(p));
    return a;
}
__device__ __forceinline__ void split2(float x0, float x1, __nv_bfloat162& hi, __nv_bfloat162& lo) {
    hi = __floats2bfloat162_rn(x0, x1);
    lo = __floats2bfloat162_rn(x0 - __bfloat162float(__low2bfloat16(hi)),
                               x1 - __bfloat162float(__high2bfloat16(hi)));
}
__device__ __forceinline__ float2 bf2f(uint32_t u) {
    __nv_bfloat162 b = *(__nv_bfloat162*)&u;
    return __bfloat1622float2(b);
}

#define AST 72   // smem row stride in bf16 (conflict-free for ldmatrix)

#define QKV_SMEM_BYTES (4 * 128 * AST * 2 + 512)
#define PROJ_SMEM_BYTES ((2 * 128 * AST + 2 * 64 * AST) * 2 + 256)

// ============================================================================
// Kernel 1 (HMMA + ldmatrix): qkv+skip GEMM. q,x_r -> g_buf fp32; k,v -> g_kv bf16.
// ============================================================================
__global__ __launch_bounds__(256) void gemm_qkvs_mma(
    const float* __restrict__ x,
    const float* __restrict__ Wq, const float* __restrict__ bq,
    const float* __restrict__ Wk, const float* __restrict__ bk,
    const float* __restrict__ Wv, const float* __restrict__ bv,
    const float* __restrict__ Wsk, const float* __restrict__ bsk)
{
    extern __shared__ __nv_bfloat16 sm[];
    __nv_bfloat16* Ahi = sm;
    __nv_bfloat16* Alo = sm + 128 * AST;
    __nv_bfloat16* Whi = sm + 2 * 128 * AST;
    __nv_bfloat16* Wlo = sm + 3 * 128 * AST;
    float* sbias = (float*)(sm + 4 * 128 * AST);

    int t = threadIdx.x;
    int bx = blockIdx.x, by = blockIdx.y;
    int c0 = bx * 128;
    int which = c0 >> 8, dbase = c0 & 255;
    const float* W = (which == 0) ? Wq : (which == 1) ? Wk : (which == 2) ? Wv : Wsk;
    const float* B = (which == 0) ? bq : (which == 1) ? bk : (which == 2) ? bv : bsk;
    int row0 = by * 128;

    if (t < 128) sbias[t] = B[dbase + t];

#pragma unroll
    for (int i = 0; i < 8; i++) {
        int idx = t + i * 256;
        int r = idx >> 4, qd = idx & 15;
        int so = r * AST + qd * 4;
        float4 v = make_float4(0.f, 0.f, 0.f, 0.f);
        int rg = row0 + r;
        if (rg < NN) v = *(const float4*)(x + (size_t)rg * 64 + qd * 4);
        __nv_bfloat162 h0, l0, h1, l1;
        split2(v.x, v.y, h0, l0);
        split2(v.z, v.w, h1, l1);
        *(__nv_bfloat162*)(Ahi + so) = h0;  *(__nv_bfloat162*)(Ahi + so + 2) = h1;
        *(__nv_bfloat162*)(Alo + so) = l0;  *(__nv_bfloat162*)(Alo + so + 2) = l1;
        float4 w4 = *(const float4*)(W + (size_t)(dbase + r) * 64 + qd * 4);
        split2(w4.x, w4.y, h0, l0);
        split2(w4.z, w4.w, h1, l1);
        *(__nv_bfloat162*)(Whi + so) = h0;  *(__nv_bfloat162*)(Whi + so + 2) = h1;
        *(__nv_bfloat162*)(Wlo + so) = l0;  *(__nv_bfloat162*)(Wlo + so + 2) = l1;
    }
    __syncthreads();

    int wid = t >> 5, lane = t & 31;
    int g = lane >> 2, tq = lane & 3;
    int r0 = (wid & 3) * 32;
    int cw = (wid >> 2) * 64;

    int aoff0 = (r0 + (lane & 15)) * AST + (lane >> 4) * 8;
    int aoff1 = (r0 + 16 + (lane & 15)) * AST + (lane >> 4) * 8;
    uint32_t aHi0 = smem_u32(Ahi) + aoff0 * 2, aHi1 = smem_u32(Ahi) + aoff1 * 2;
    uint32_t aLo0 = smem_u32(Alo) + aoff0 * 2, aLo1 = smem_u32(Alo) + aoff1 * 2;
    int bcol = cw + ((lane >> 4) << 3) + (lane & 7);
    int bkh = ((lane >> 3) & 1) * 8;
    uint32_t bHiB = smem_u32(Whi) + (bcol * AST + bkh) * 2;
    uint32_t bLoB = smem_u32(Wlo) + (bcol * AST + bkh) * 2;

    float acc[2][8][4];
#pragma unroll
    for (int mt = 0; mt < 2; mt++)
#pragma unroll
        for (int nt = 0; nt < 8; nt++)
#pragma unroll
            for (int j = 0; j < 4; j++) acc[mt][nt][j] = 0.f;

#pragma unroll
    for (int ks = 0; ks < 4; ks++) {
        uint32_t kbB = ks * 32;
        uint32_t ahi[2][4], alo[2][4];
        LDMX4(ahi[0], aHi0 + kbB);
        LDMX4(ahi[1], aHi1 + kbB);
        LDMX4(alo[0], aLo0 + kbB);
        LDMX4(alo[1], aLo1 + kbB);
#pragma unroll
        for (int ntg = 0; ntg < 4; ntg++) {
            uint32_t cgB = (uint32_t)(ntg * 16 * AST * 2);
            uint32_t bh[4], bl[4];
            LDMX4(bh, bHiB + cgB + kbB);
            LDMX4(bl, bLoB + cgB + kbB);
#pragma unroll
            for (int mt = 0; mt < 2; mt++) {
                mma16816(acc[mt][2 * ntg],     ahi[mt], bh);
                mma16816(acc[mt][2 * ntg + 1], ahi[mt], bh + 2);
                mma16816(acc[mt][2 * ntg],     ahi[mt], bl);
                mma16816(acc[mt][2 * ntg + 1], ahi[mt], bl + 2);
                mma16816(acc[mt][2 * ntg],     alo[mt], bh);
                mma16816(acc[mt][2 * ntg + 1], alo[mt], bh + 2);
            }
        }
    }

    bool isf32 = (which == 0) || (which == 3);
    int f32off = (which == 0) ? 0 : 256;   // q at 0, x_r at 256 in g_buf
    int kvoff  = (which == 1) ? 0 : 256;   // k at 0, v at 256 in g_kv
#pragma unroll
    for (int mt = 0; mt < 2; mt++) {
        int rA = row0 + r0 + mt * 16 + g;
        int rB = rA + 8;
#pragma unroll
        for (int nt = 0; nt < 8; nt++) {
            int lc = cw + nt * 8 + tq * 2;
            float b0 = sbias[lc], b1 = sbias[lc + 1];
            int ch = dbase + lc;
            if (rA < NN) {
                if (isf32)
                    *(float2*)(g_buf + (size_t)rA * 512 + f32off + ch) =
                        make_float2(acc[mt][nt][0] + b0, acc[mt][nt][1] + b1);
                else
                    *(__nv_bfloat162*)(g_kv + (size_t)rA * 512 + kvoff + ch) =
                        __floats2bfloat162_rn(acc[mt][nt][0] + b0, acc[mt][nt][1] + b1);
            }
            if (rB < NN) {
                if (isf32)
                    *(float2*)(g_buf + (size_t)rB * 512 + f32off + ch) =
                        make_float2(acc[mt][nt][2] + b0, acc[mt][nt][3] + b1);
                else
                    *(__nv_bfloat162*)(g_kv + (size_t)rB * 512 + kvoff + ch) =
                        __floats2bfloat162_rn(acc[mt][nt][2] + b0, acc[mt][nt][3] + b1);
            }
        }
    }
}

// ============================================================================
// CSR build: histogram -> exclusive scan (zeroes deg) -> scatter
// ============================================================================
__global__ __launch_bounds__(256) void hist_kernel(const int* __restrict__ ei)
{
    int e = blockIdx.x * 256 + threadIdx.x;
    if (e < EE) atomicAdd(&g_deg[ei[EE + e]], 1);
}

__global__ __launch_bounds__(1024) void scan_kernel()
{
    __shared__ int wsum[32];
    __shared__ int carryS;
    int t = threadIdx.x;
    int lane = t & 31, w = t >> 5;
    if (t == 0) carryS = 0;
    __syncthreads();
    for (int base = 0; base < NN; base += 1024) {
        int i = base + t;
        int v = (i < NN) ? g_deg[i] : 0;
        if (i < NN) g_deg[i] = 0;               // self-clean for next replay
        int xv = v;
#pragma unroll
        for (int off = 1; off < 32; off <<= 1) {
            int u = __shfl_up_sync(0xffffffffu, xv, off);
            if (lane >= off) xv += u;
        }
        if (lane == 31) wsum[w] = xv;
        __syncthreads();
        if (w == 0) {
            int y = wsum[lane];
#pragma unroll
            for (int off = 1; off < 32; off <<= 1) {
                int u = __shfl_up_sync(0xffffffffu, y, off);
                if (lane >= off) y += u;
            }
            wsum[lane] = y;
        }
        __syncthreads();
        int incl = xv + (w ? wsum[w - 1] : 0);
        int c = carryS;
        if (i < NN) g_start[i] = c + incl - v;
        __syncthreads();
        if (t == 0) carryS = c + wsum[31];
        __syncthreads();
    }
    if (t == 0) g_start[NN] = carryS;
}

__global__ __launch_bounds__(256) void scatter_kernel(const int* __restrict__ ei)
{
    int e = blockIdx.x * 256 + threadIdx.x;
    if (e < EE) {
        int d = ei[EE + e];
        int s = ei[e];
        int pos = g_start[d] + atomicAdd(&g_cur[d], 1);
        g_esrc[pos] = s;
    }
}

// ============================================================================
// Kernel 3: warp-per-dst online-softmax attention + beta-gate + LN (R11 form).
// Also zeroes this node's scatter cursor (self-clean for next replay).
// ============================================================================
__global__ __launch_bounds__(256) void attn_kernel(
    const float* __restrict__ Wbeta,
    const float* __restrict__ lng, const float* __restrict__ lnb)
{
    __shared__ float sWb[768];
    __shared__ float sg[256], sb[256];
    int t = threadIdx.x;
    for (int i = t; i < 768; i += 256) sWb[i] = Wbeta[i];
    if (t < 256) { sg[t] = lng[t]; sb[t] = lnb[t]; }
    __syncthreads();

    int warp = t >> 5, lane = t & 31;
    int node = blockIdx.x * 8 + warp;
    if (node >= NN) return;
    if (lane == 0) g_cur[node] = 0;            // self-clean for next replay

    int c0 = lane * 8;
    const float* qp = g_buf + (size_t)node * 512 + c0;
    float q[8];
    *(float4*)(q)     = *(const float4*)(qp);
    *(float4*)(q + 4) = *(const float4*)(qp + 4);
#pragma unroll
    for (int u = 0; u < 8; u++) q[u] *= 0.125f;   // 1/sqrt(64)

    float m = -1e30f, ssum = 0.f;
    float acc[8];
#pragma unroll
    for (int u = 0; u < 8; u++) acc[u] = 0.f;

    int e0 = g_start[node], e1 = g_start[node + 1];
    int src = (e0 < e1) ? g_esrc[e0] : 0;
    for (int e = e0; e < e1; e++) {
        const __nv_bfloat16* kp = g_kv + (size_t)src * 512 + c0;
        uint4 kraw = *(const uint4*)(kp);         // 8 bf16 k
        uint4 vraw = *(const uint4*)(kp + 256);   // 8 bf16 v
        int nsrc = (e + 1 < e1) ? g_esrc[e + 1] : 0;

        float2 k0 = bf2f(kraw.x), k1 = bf2f(kraw.y), k2 = bf2f(kraw.z), k3 = bf2f(kraw.w);
        float p = q[0] * k0.x + q[1] * k0.y + q[2] * k1.x + q[3] * k1.y
                + q[4] * k2.x + q[5] * k2.y + q[6] * k3.x + q[7] * k3.y;
        p += __shfl_xor_sync(0xffffffffu, p, 1, 8);
        p += __shfl_xor_sync(0xffffffffu, p, 2, 8);
        p += __shfl_xor_sync(0xffffffffu, p, 4, 8);
        float mn = fmaxf(m, p);
        float sc = __expf(m - mn);
        float wgt = __expf(p - mn);
        m = mn;
        ssum = ssum * sc + wgt;
        float2 v0 = bf2f(vraw.x), v1 = bf2f(vraw.y), v2 = bf2f(vraw.z), v3 = bf2f(vraw.w);
        acc[0] = acc[0] * sc + wgt * v0.x;
        acc[1] = acc[1] * sc + wgt * v0.y;
        acc[2] = acc[2] * sc + wgt * v1.x;
        acc[3] = acc[3] * sc + wgt * v1.y;
        acc[4] = acc[4] * sc + wgt * v2.x;
        acc[5] = acc[5] * sc + wgt * v2.y;
        acc[6] = acc[6] * sc + wgt * v3.x;
        acc[7] = acc[7] * sc + wgt * v3.y;
        src = nsrc;
    }
    float inv = 1.f / (ssum + 1e-16f);
    float outv[8];
#pragma unroll
    for (int u = 0; u < 8; u++) outv[u] = acc[u] * inv;

    const float* xp = g_buf + (size_t)node * 512 + 256 + c0;
    float xr[8];
    *(float4*)(xr)     = *(const float4*)(xp);
    *(float4*)(xr + 4) = *(const float4*)(xp + 4);

    float part = 0.f;
#pragma unroll
    for (int u = 0; u < 8; u++) {
        int c = c0 + u;
        part += outv[u] * sWb[c] + xr[u] * sWb[256 + c] + (outv[u] - xr[u]) * sWb[512 + c];
    }
#pragma unroll
    for (int off = 16; off > 0; off >>= 1)
        part += __shfl_xor_sync(0xffffffffu, part, off);
    float beta = 1.f / (1.f + __expf(-part));

    float h[8], sum = 0.f, sq = 0.f;
#pragma unroll
    for (int u = 0; u < 8; u++) {
        h[u] = beta * xr[u] + (1.f - beta) * outv[u];
        sum += h[u];
        sq += h[u] * h[u];
    }
#pragma unroll
    for (int off = 16; off > 0; off >>= 1) {
        sum += __shfl_xor_sync(0xffffffffu, sum, off);
        sq  += __shfl_xor_sync(0xffffffffu, sq, off);
    }
    float mu = sum * (1.f / 256.f);
    float var = sq * (1.f / 256.f) - mu * mu;
    float rstd = rsqrtf(var + 1e-5f);

    __nv_bfloat162 hh[4], hl[4];
#pragma unroll
    for (int u = 0; u < 4; u++) {
        int c = c0 + 2 * u;
        float o0 = (h[2 * u]     - mu) * rstd * sg[c]     + sb[c];
        float o1 = (h[2 * u + 1] - mu) * rstd * sg[c + 1] + sb[c + 1];
        split2(o0, o1, hh[u], hl[u]);
    }
    *(uint4*)(g_hhi + (size_t)node * 256 + c0) = *(uint4*)hh;
    *(uint4*)(g_hlo + (size_t)node * 256 + c0) = *(uint4*)hl;
}

// ============================================================================
// Kernel 4 (HMMA + ldmatrix): out[n,64] = relu(h @ Wp^T + bp + x)
// ============================================================================
__global__ __launch_bounds__(256) void gemm_proj_mma(
    const float* __restrict__ x,
    const float* __restrict__ Wp, const float* __restrict__ bp,
    float* __restrict__ out)
{
    extern __shared__ __nv_bfloat16 sm[];
    __nv_bfloat16* Hhi = sm;
    __nv_bfloat16* Hlo = sm + 128 * AST;
    __nv_bfloat16* Phi = sm + 2 * 128 * AST;
    __nv_bfloat16* Plo = sm + 2 * 128 * AST + 64 * AST;
    float* sbias = (float*)(sm + 2 * 128 * AST + 2 * 64 * AST);

    int t = threadIdx.x;
    int row0 = blockIdx.x * 128;
    if (t < 64) sbias[t] = bp[t];

    int wid = t >> 5, lane = t & 31;
    int g = lane >> 2, tq = lane & 3;
    int r0 = wid * 16;

    int aoff = (r0 + (lane & 15)) * AST + (lane >> 4) * 8;
    uint32_t aHiB = smem_u32(Hhi) + aoff * 2;
    uint32_t aLoB = smem_u32(Hlo) + aoff * 2;
    int bcol = ((lane >> 4) << 3) + (lane & 7);
    int bkh = ((lane >> 3) & 1) * 8;
    uint32_t bHiB = smem_u32(Phi) + (bcol * AST + bkh) * 2;
    uint32_t bLoB = smem_u32(Plo) + (bcol * AST + bkh) * 2;

    float acc[8][4];
#pragma unroll
    for (int nt = 0; nt < 8; nt++)
#pragma unroll
        for (int j = 0; j < 4; j++) acc[nt][j] = 0.f;

    for (int kc = 0; kc < 256; kc += 64) {
        __syncthreads();
#pragma unroll
        for (int i = 0; i < 4; i++) {
            int u = t + i * 256;
            int r = u >> 3, qd = u & 7;
            int rg = row0 + r;
            uint4 vh = make_uint4(0, 0, 0, 0), vl = make_uint4(0, 0, 0, 0);
            if (rg < NN) {
                vh = *(const uint4*)(g_hhi + (size_t)rg * 256 + kc + qd * 8);
                vl = *(const uint4*)(g_hlo + (size_t)rg * 256 + kc + qd * 8);
            }
            *(uint4*)(Hhi + r * AST + qd * 8) = vh;
            *(uint4*)(Hlo + r * AST + qd * 8) = vl;
        }
#pragma unroll
        for (int i = 0; i < 4; i++) {
            int u = t + i * 256;
            int r = u >> 4, qd = u & 15;
            float4 w4 = *(const float4*)(Wp + (size_t)r * 256 + kc + qd * 4);
            __nv_bfloat162 h0, l0, h1, l1;
            split2(w4.x, w4.y, h0, l0);
            split2(w4.z, w4.w, h1, l1);
            int so = r * AST + qd * 4;
            *(__nv_bfloat162*)(Phi + so) = h0;  *(__nv_bfloat162*)(Phi + so + 2) = h1;
            *(__nv_bfloat162*)(Plo + so) = l0;  *(__nv_bfloat162*)(Plo + so + 2) = l1;
        }
        __syncthreads();

#pragma unroll
        for (int ks = 0; ks < 4; ks++) {
            uint32_t kbB = ks * 32;
            uint32_t ahi[4], alo[4];
            LDMX4(ahi, aHiB + kbB);
            LDMX4(alo, aLoB + kbB);
#pragma unroll
            for (int ntg = 0; ntg < 4; ntg++) {
                uint32_t cgB = (uint32_t)(ntg * 16 * AST * 2);
                uint32_t bh[4], bl[4];
                LDMX4(bh, bHiB + cgB + kbB);
                LDMX4(bl, bLoB + cgB + kbB);
                mma16816(acc[2 * ntg],     ahi, bh);
                mma16816(acc[2 * ntg + 1], ahi, bh + 2);
                mma16816(acc[2 * ntg],     ahi, bl);
                mma16816(acc[2 * ntg + 1], ahi, bl + 2);
                mma16816(acc[2 * ntg],     alo, bh);
                mma16816(acc[2 * ntg + 1], alo, bh + 2);
            }
        }
    }

    int rA = row0 + r0 + g;
    int rB = rA + 8;
#pragma unroll
    for (int nt = 0; nt < 8; nt++) {
        int lc = nt * 8 + tq * 2;
        float b0 = sbias[lc], b1 = sbias[lc + 1];
        if (rA < NN) {
            float2 xv = *(const float2*)(x + (size_t)rA * 64 + lc);
            *(float2*)(out + (size_t)rA * 64 + lc) =
                make_float2(fmaxf(acc[nt][0] + b0 + xv.x, 0.f), fmaxf(acc[nt][1] + b1 + xv.y, 0.f));
        }
        if (rB < NN) {
            float2 xv = *(const float2*)(x + (size_t)rB * 64 + lc);
            *(float2*)(out + (size_t)rB * 64 + lc) =
                make_float2(fmaxf(acc[nt][2] + b0 + xv.x, 0.f), fmaxf(acc[nt][3] + b1 + xv.y, 0.f));
        }
    }
}

// ============================================================================
// Serial launch order; no memset (globals self-clean across replays).
// attn is the 5th enqueued op -> lands in the ncu capture slot.
// ============================================================================
extern "C" void kernel_launch(void* const* d_in, const int* in_sizes, int n_in,
                              void* d_out, int out_size)
{
    const float* x     = (const float*)d_in[0];
    const int*   ei    = (const int*)d_in[1];
    const float* Wq    = (const float*)d_in[2];
    const float* bq    = (const float*)d_in[3];
    const float* Wk    = (const float*)d_in[4];
    const float* bk    = (const float*)d_in[5];
    const float* Wv    = (const float*)d_in[6];
    const float* bv    = (const float*)d_in[7];
    const float* Wsk   = (const float*)d_in[8];
    const float* bsk   = (const float*)d_in[9];
    const float* Wbeta = (const float*)d_in[10];
    const float* lng   = (const float*)d_in[11];
    const float* lnb   = (const float*)d_in[12];
    const float* Wp    = (const float*)d_in[13];
    const float* bp    = (const float*)d_in[14];
    float* out = (float*)d_out;

    static int attr_set = 0;
    if (!attr_set) {
        cudaFuncSetAttribute(gemm_qkvs_mma,
                             cudaFuncAttributeMaxDynamicSharedMemorySize, QKV_SMEM_BYTES);
        cudaFuncSetAttribute(gemm_proj_mma,
                             cudaFuncAttributeMaxDynamicSharedMemorySize, PROJ_SMEM_BYTES);
        attr_set = 1;
    }

    hist_kernel<<<2500, 256>>>(ei);                              // 1
    scan_kernel<<<1, 1024>>>();                                  // 2
    scatter_kernel<<<2500, 256>>>(ei);                           // 3
    gemm_qkvs_mma<<<dim3(8, 391), 256, QKV_SMEM_BYTES>>>(x, Wq, bq, Wk, bk, Wv, bv, Wsk, bsk); // 4
    attn_kernel<<<6250, 256>>>(Wbeta, lng, lnb);                 // 5  <- profiled
    gemm_proj_mma<<<391, 256, PROJ_SMEM_BYTES>>>(x, Wp, bp, out); // 6
}

// round 16
// speedup vs baseline: 1.3159x; 1.1663x over previous
#include <cuda_runtime.h>
#include <cuda_bf16.h>
#include <cstdint>

#define NN 50000
#define EE 640000
#define NB 49   // scan blocks of 1024 covering 50176 >= NN

// ---- scratch (static device globals; zero-inited at load, self-cleaned each run) ----
__device__ __align__(16) float g_buf[(size_t)NN * 512];           // [q|x_r] fp32, 102.4MB
__device__ __align__(16) __nv_bfloat16 g_kv[(size_t)NN * 512];    // [k|v] bf16, 51.2MB (L2-resident)
__device__ __align__(16) __nv_bfloat16 g_hhi[(size_t)NN * 256];   // h hi plane
__device__ __align__(16) __nv_bfloat16 g_hlo[(size_t)NN * 256];   // h lo plane
__device__ int g_deg[NN];        // degree histogram (zeroed by scan1 after use)
__device__ int g_cur[NN];        // scatter cursors (zeroed by attn_kernel after use)
__device__ int g_start[NN + 1];
__device__ int g_bsum[64];       // per-block scan totals
__device__ int g_esrc[EE];

// ---- warp-level bf16 MMA (m16n8k16, fp32 accum) ----
__device__ __forceinline__ void mma16816(float* c, const uint32_t* a, const uint32_t* b) {
    asm volatile(
        "mma.sync.aligned.m16n8k16.row.col.f32.bf16.bf16.f32 "
        "{%0,%1,%2,%3}, {%4,%5,%6,%7}, {%8,%9}, {%0,%1,%2,%3};\n"
        : "+f"(c[0]), "+f"(c[1]), "+f"(c[2]), "+f"(c[3])
        : "r"(a[0]), "r"(a[1]), "r"(a[2]), "r"(a[3]), "r"(b[0]), "r"(b[1]));
}
#define LDMX4(r, addr)                                                            \
    asm volatile("ldmatrix.sync.aligned.m8n8.x4.shared.b16 {%0,%1,%2,%3}, [%4];"  \
        : "=r"((r)[0]), "=r"((r)[1]), "=r"((r)[2]), "=r"((r)[3]) : "r"(addr))

__device__ __forceinline__ uint32_t smem_u32(const void* p) {
    uint32_t a;
    asm("{ .reg .u64 t; cvta.to.shared.u64 t, %1; cvt.u32.u64 %0, t; }" : "=r"(a) : "l"(p));
    return a;
}
__device__ __forceinline__ void split2(float x0, float x1, __nv_bfloat162& hi, __nv_bfloat162& lo) {
    hi = __floats2bfloat162_rn(x0, x1);
    lo = __floats2bfloat162_rn(x0 - __bfloat162float(__low2bfloat16(hi)),
                               x1 - __bfloat162float(__high2bfloat16(hi)));
}
__device__ __forceinline__ float2 bf2f(uint32_t u) {
    __nv_bfloat162 b = *(__nv_bfloat162*)&u;
    return __bfloat1622float2(b);
}

#define AST 72   // smem row stride in bf16 (conflict-free for ldmatrix)

#define QKV_SMEM_BYTES (4 * 128 * AST * 2 + 512)
#define PROJ_SMEM_BYTES ((2 * 128 * AST + 2 * 64 * AST) * 2 + 256)

// ============================================================================
// Kernel 1 (HMMA + ldmatrix): qkv+skip GEMM. q,x_r -> g_buf fp32; k,v -> g_kv bf16.
// ============================================================================
__global__ __launch_bounds__(256) void gemm_qkvs_mma(
    const float* __restrict__ x,
    const float* __restrict__ Wq, const float* __restrict__ bq,
    const float* __restrict__ Wk, const float* __restrict__ bk,
    const float* __restrict__ Wv, const float* __restrict__ bv,
    const float* __restrict__ Wsk, const float* __restrict__ bsk)
{
    extern __shared__ __nv_bfloat16 sm[];
    __nv_bfloat16* Ahi = sm;
    __nv_bfloat16* Alo = sm + 128 * AST;
    __nv_bfloat16* Whi = sm + 2 * 128 * AST;
    __nv_bfloat16* Wlo = sm + 3 * 128 * AST;
    float* sbias = (float*)(sm + 4 * 128 * AST);

    int t = threadIdx.x;
    int bx = blockIdx.x, by = blockIdx.y;
    int c0 = bx * 128;
    int which = c0 >> 8, dbase = c0 & 255;
    const float* W = (which == 0) ? Wq : (which == 1) ? Wk : (which == 2) ? Wv : Wsk;
    const float* B = (which == 0) ? bq : (which == 1) ? bk : (which == 2) ? bv : bsk;
    int row0 = by * 128;

    if (t < 128) sbias[t] = B[dbase + t];

#pragma unroll
    for (int i = 0; i < 8; i++) {
        int idx = t + i * 256;
        int r = idx >> 4, qd = idx & 15;
        int so = r * AST + qd * 4;
        float4 v = make_float4(0.f, 0.f, 0.f, 0.f);
        int rg = row0 + r;
        if (rg < NN) v = *(const float4*)(x + (size_t)rg * 64 + qd * 4);
        __nv_bfloat162 h0, l0, h1, l1;
        split2(v.x, v.y, h0, l0);
        split2(v.z, v.w, h1, l1);
        *(__nv_bfloat162*)(Ahi + so) = h0;  *(__nv_bfloat162*)(Ahi + so + 2) = h1;
        *(__nv_bfloat162*)(Alo + so) = l0;  *(__nv_bfloat162*)(Alo + so + 2) = l1;
        float4 w4 = *(const float4*)(W + (size_t)(dbase + r) * 64 + qd * 4);
        split2(w4.x, w4.y, h0, l0);
        split2(w4.z, w4.w, h1, l1);
        *(__nv_bfloat162*)(Whi + so) = h0;  *(__nv_bfloat162*)(Whi + so + 2) = h1;
        *(__nv_bfloat162*)(Wlo + so) = l0;  *(__nv_bfloat162*)(Wlo + so + 2) = l1;
    }
    __syncthreads();

    int wid = t >> 5, lane = t & 31;
    int g = lane >> 2, tq = lane & 3;
    int r0 = (wid & 3) * 32;
    int cw = (wid >> 2) * 64;

    int aoff0 = (r0 + (lane & 15)) * AST + (lane >> 4) * 8;
    int aoff1 = (r0 + 16 + (lane & 15)) * AST + (lane >> 4) * 8;
    uint32_t aHi0 = smem_u32(Ahi) + aoff0 * 2, aHi1 = smem_u32(Ahi) + aoff1 * 2;
    uint32_t aLo0 = smem_u32(Alo) + aoff0 * 2, aLo1 = smem_u32(Alo) + aoff1 * 2;
    int bcol = cw + ((lane >> 4) << 3) + (lane & 7);
    int bkh = ((lane >> 3) & 1) * 8;
    uint32_t bHiB = smem_u32(Whi) + (bcol * AST + bkh) * 2;
    uint32_t bLoB = smem_u32(Wlo) + (bcol * AST + bkh) * 2;

    float acc[2][8][4];
#pragma unroll
    for (int mt = 0; mt < 2; mt++)
#pragma unroll
        for (int nt = 0; nt < 8; nt++)
#pragma unroll
            for (int j = 0; j < 4; j++) acc[mt][nt][j] = 0.f;

#pragma unroll
    for (int ks = 0; ks < 4; ks++) {
        uint32_t kbB = ks * 32;
        uint32_t ahi[2][4], alo[2][4];
        LDMX4(ahi[0], aHi0 + kbB);
        LDMX4(ahi[1], aHi1 + kbB);
        LDMX4(alo[0], aLo0 + kbB);
        LDMX4(alo[1], aLo1 + kbB);
#pragma unroll
        for (int ntg = 0; ntg < 4; ntg++) {
            uint32_t cgB = (uint32_t)(ntg * 16 * AST * 2);
            uint32_t bh[4], bl[4];
            LDMX4(bh, bHiB + cgB + kbB);
            LDMX4(bl, bLoB + cgB + kbB);
#pragma unroll
            for (int mt = 0; mt < 2; mt++) {
                mma16816(acc[mt][2 * ntg],     ahi[mt], bh);
                mma16816(acc[mt][2 * ntg + 1], ahi[mt], bh + 2);
                mma16816(acc[mt][2 * ntg],     ahi[mt], bl);
                mma16816(acc[mt][2 * ntg + 1], ahi[mt], bl + 2);
                mma16816(acc[mt][2 * ntg],     alo[mt], bh);
                mma16816(acc[mt][2 * ntg + 1], alo[mt], bh + 2);
            }
        }
    }

    bool isf32 = (which == 0) || (which == 3);
    int f32off = (which == 0) ? 0 : 256;   // q at 0, x_r at 256 in g_buf
    int kvoff  = (which == 1) ? 0 : 256;   // k at 0, v at 256 in g_kv
#pragma unroll
    for (int mt = 0; mt < 2; mt++) {
        int rA = row0 + r0 + mt * 16 + g;
        int rB = rA + 8;
#pragma unroll
        for (int nt = 0; nt < 8; nt++) {
            int lc = cw + nt * 8 + tq * 2;
            float b0 = sbias[lc], b1 = sbias[lc + 1];
            int ch = dbase + lc;
            if (rA < NN) {
                if (isf32)
                    *(float2*)(g_buf + (size_t)rA * 512 + f32off + ch) =
                        make_float2(acc[mt][nt][0] + b0, acc[mt][nt][1] + b1);
                else
                    *(__nv_bfloat162*)(g_kv + (size_t)rA * 512 + kvoff + ch) =
                        __floats2bfloat162_rn(acc[mt][nt][0] + b0, acc[mt][nt][1] + b1);
            }
            if (rB < NN) {
                if (isf32)
                    *(float2*)(g_buf + (size_t)rB * 512 + f32off + ch) =
                        make_float2(acc[mt][nt][2] + b0, acc[mt][nt][3] + b1);
                else
                    *(__nv_bfloat162*)(g_kv + (size_t)rB * 512 + kvoff + ch) =
                        __floats2bfloat162_rn(acc[mt][nt][2] + b0, acc[mt][nt][3] + b1);
            }
        }
    }
}

// ============================================================================
// CSR build: histogram -> 3-phase multi-block scan -> scatter
// ============================================================================
__global__ __launch_bounds__(256) void hist_kernel(const int* __restrict__ ei)
{
    int e = blockIdx.x * 256 + threadIdx.x;
    if (e < EE) atomicAdd(&g_deg[ei[EE + e]], 1);
}

// phase 1: block-local exclusive scan (1024/block), block totals to g_bsum.
__global__ __launch_bounds__(1024) void scan1_kernel()
{
    __shared__ int wsum[32];
    int t = threadIdx.x;
    int lane = t & 31, w = t >> 5;
    int i = blockIdx.x * 1024 + t;
    int v = (i < NN) ? g_deg[i] : 0;
    if (i < NN) g_deg[i] = 0;                  // self-clean for next replay
    int xv = v;
#pragma unroll
    for (int off = 1; off < 32; off <<= 1) {
        int u = __shfl_up_sync(0xffffffffu, xv, off);
        if (lane >= off) xv += u;
    }
    if (lane == 31) wsum[w] = xv;
    __syncthreads();
    if (w == 0) {
        int y = wsum[lane];
#pragma unroll
        for (int off = 1; off < 32; off <<= 1) {
            int u = __shfl_up_sync(0xffffffffu, y, off);
            if (lane >= off) y += u;
        }
        wsum[lane] = y;
    }
    __syncthreads();
    int incl = xv + (w ? wsum[w - 1] : 0);
    if (i < NN) g_start[i] = incl - v;         // block-local exclusive
    if (t == 1023) g_bsum[blockIdx.x] = incl;  // block total
}

// phase 2: exclusive scan of the NB block totals; writes g_start[NN].
__global__ __launch_bounds__(64) void scan2_kernel()
{
    __shared__ int ws[2];
    int t = threadIdx.x;
    int lane = t & 31, w = t >> 5;
    int v = (t < NB) ? g_bsum[t] : 0;
    int xv = v;
#pragma unroll
    for (int off = 1; off < 32; off <<= 1) {
        int u = __shfl_up_sync(0xffffffffu, xv, off);
        if (lane >= off) xv += u;
    }
    if (lane == 31) ws[w] = xv;
    __syncthreads();
    int incl = xv + (w ? ws[0] : 0);
    if (t < NB) g_bsum[t] = incl - v;          // exclusive block offsets
    if (t == 63) g_start[NN] = incl;           // grand total (= EE)
}

// phase 3: add block offsets.
__global__ __launch_bounds__(1024) void scan3_kernel()
{
    int i = blockIdx.x * 1024 + threadIdx.x;
    if (i < NN) g_start[i] += g_bsum[blockIdx.x];
}

__global__ __launch_bounds__(256) void scatter_kernel(const int* __restrict__ ei)
{
    int e = blockIdx.x * 256 + threadIdx.x;
    if (e < EE) {
        int d = ei[EE + e];
        int s = ei[e];
        int pos = g_start[d] + atomicAdd(&g_cur[d], 1);
        g_esrc[pos] = s;
    }
}

// ============================================================================
// Kernel 3: warp-per-dst online-softmax attention + beta-gate + LN (R11 form).
// ============================================================================
__global__ __launch_bounds__(256) void attn_kernel(
    const float* __restrict__ Wbeta,
    const float* __restrict__ lng, const float* __restrict__ lnb)
{
    __shared__ float sWb[768];
    __shared__ float sg[256], sb[256];
    int t = threadIdx.x;
    for (int i = t; i < 768; i += 256) sWb[i] = Wbeta[i];
    if (t < 256) { sg[t] = lng[t]; sb[t] = lnb[t]; }
    __syncthreads();

    int warp = t >> 5, lane = t & 31;
    int node = blockIdx.x * 8 + warp;
    if (node >= NN) return;
    if (lane == 0) g_cur[node] = 0;            // self-clean for next replay

    int c0 = lane * 8;
    const float* qp = g_buf + (size_t)node * 512 + c0;
    float q[8];
    *(float4*)(q)     = *(const float4*)(qp);
    *(float4*)(q + 4) = *(const float4*)(qp + 4);
#pragma unroll
    for (int u = 0; u < 8; u++) q[u] *= 0.125f;   // 1/sqrt(64)

    float m = -1e30f, ssum = 0.f;
    float acc[8];
#pragma unroll
    for (int u = 0; u < 8; u++) acc[u] = 0.f;

    int e0 = g_start[node], e1 = g_start[node + 1];
    int src = (e0 < e1) ? g_esrc[e0] : 0;
    for (int e = e0; e < e1; e++) {
        const __nv_bfloat16* kp = g_kv + (size_t)src * 512 + c0;
        uint4 kraw = *(const uint4*)(kp);         // 8 bf16 k
        uint4 vraw = *(const uint4*)(kp + 256);   // 8 bf16 v
        int nsrc = (e + 1 < e1) ? g_esrc[e + 1] : 0;

        float2 k0 = bf2f(kraw.x), k1 = bf2f(kraw.y), k2 = bf2f(kraw.z), k3 = bf2f(kraw.w);
        float p = q[0] * k0.x + q[1] * k0.y + q[2] * k1.x + q[3] * k1.y
                + q[4] * k2.x + q[5] * k2.y + q[6] * k3.x + q[7] * k3.y;
        p += __shfl_xor_sync(0xffffffffu, p, 1, 8);
        p += __shfl_xor_sync(0xffffffffu, p, 2, 8);
        p += __shfl_xor_sync(0xffffffffu, p, 4, 8);
        float mn = fmaxf(m, p);
        float sc = __expf(m - mn);
        float wgt = __expf(p - mn);
        m = mn;
        ssum = ssum * sc + wgt;
        float2 v0 = bf2f(vraw.x), v1 = bf2f(vraw.y), v2 = bf2f(vraw.z), v3 = bf2f(vraw.w);
        acc[0] = acc[0] * sc + wgt * v0.x;
        acc[1] = acc[1] * sc + wgt * v0.y;
        acc[2] = acc[2] * sc + wgt * v1.x;
        acc[3] = acc[3] * sc + wgt * v1.y;
        acc[4] = acc[4] * sc + wgt * v2.x;
        acc[5] = acc[5] * sc + wgt * v2.y;
        acc[6] = acc[6] * sc + wgt * v3.x;
        acc[7] = acc[7] * sc + wgt * v3.y;
        src = nsrc;
    }
    float inv = 1.f / (ssum + 1e-16f);
    float outv[8];
#pragma unroll
    for (int u = 0; u < 8; u++) outv[u] = acc[u] * inv;

    const float* xp = g_buf + (size_t)node * 512 + 256 + c0;
    float xr[8];
    *(float4*)(xr)     = *(const float4*)(xp);
    *(float4*)(xr + 4) = *(const float4*)(xp + 4);

    float part = 0.f;
#pragma unroll
    for (int u = 0; u < 8; u++) {
        int c = c0 + u;
        part += outv[u] * sWb[c] + xr[u] * sWb[256 + c] + (outv[u] - xr[u]) * sWb[512 + c];
    }
#pragma unroll
    for (int off = 16; off > 0; off >>= 1)
        part += __shfl_xor_sync(0xffffffffu, part, off);
    float beta = 1.f / (1.f + __expf(-part));

    float h[8], sum = 0.f, sq = 0.f;
#pragma unroll
    for (int u = 0; u < 8; u++) {
        h[u] = beta * xr[u] + (1.f - beta) * outv[u];
        sum += h[u];
        sq += h[u] * h[u];
    }
#pragma unroll
    for (int off = 16; off > 0; off >>= 1) {
        sum += __shfl_xor_sync(0xffffffffu, sum, off);
        sq  += __shfl_xor_sync(0xffffffffu, sq, off);
    }
    float mu = sum * (1.f / 256.f);
    float var = sq * (1.f / 256.f) - mu * mu;
    float rstd = rsqrtf(var + 1e-5f);

    __nv_bfloat162 hh[4], hl[4];
#pragma unroll
    for (int u = 0; u < 4; u++) {
        int c = c0 + 2 * u;
        float o0 = (h[2 * u]     - mu) * rstd * sg[c]     + sb[c];
        float o1 = (h[2 * u + 1] - mu) * rstd * sg[c + 1] + sb[c + 1];
        split2(o0, o1, hh[u], hl[u]);
    }
    *(uint4*)(g_hhi + (size_t)node * 256 + c0) = *(uint4*)hh;
    *(uint4*)(g_hlo + (size_t)node * 256 + c0) = *(uint4*)hl;
}

// ============================================================================
// Kernel 4 (HMMA + ldmatrix): out[n,64] = relu(h @ Wp^T + bp + x)
// ============================================================================
__global__ __launch_bounds__(256) void gemm_proj_mma(
    const float* __restrict__ x,
    const float* __restrict__ Wp, const float* __restrict__ bp,
    float* __restrict__ out)
{
    extern __shared__ __nv_bfloat16 sm[];
    __nv_bfloat16* Hhi = sm;
    __nv_bfloat16* Hlo = sm + 128 * AST;
    __nv_bfloat16* Phi = sm + 2 * 128 * AST;
    __nv_bfloat16* Plo = sm + 2 * 128 * AST + 64 * AST;
    float* sbias = (float*)(sm + 2 * 128 * AST + 2 * 64 * AST);

    int t = threadIdx.x;
    int row0 = blockIdx.x * 128;
    if (t < 64) sbias[t] = bp[t];

    int wid = t >> 5, lane = t & 31;
    int g = lane >> 2, tq = lane & 3;
    int r0 = wid * 16;

    int aoff = (r0 + (lane & 15)) * AST + (lane >> 4) * 8;
    uint32_t aHiB = smem_u32(Hhi) + aoff * 2;
    uint32_t aLoB = smem_u32(Hlo) + aoff * 2;
    int bcol = ((lane >> 4) << 3) + (lane & 7);
    int bkh = ((lane >> 3) & 1) * 8;
    uint32_t bHiB = smem_u32(Phi) + (bcol * AST + bkh) * 2;
    uint32_t bLoB = smem_u32(Plo) + (bcol * AST + bkh) * 2;

    float acc[8][4];
#pragma unroll
    for (int nt = 0; nt < 8; nt++)
#pragma unroll
        for (int j = 0; j < 4; j++) acc[nt][j] = 0.f;

    for (int kc = 0; kc < 256; kc += 64) {
        __syncthreads();
#pragma unroll
        for (int i = 0; i < 4; i++) {
            int u = t + i * 256;
            int r = u >> 3, qd = u & 7;
            int rg = row0 + r;
            uint4 vh = make_uint4(0, 0, 0, 0), vl = make_uint4(0, 0, 0, 0);
            if (rg < NN) {
                vh = *(const uint4*)(g_hhi + (size_t)rg * 256 + kc + qd * 8);
                vl = *(const uint4*)(g_hlo + (size_t)rg * 256 + kc + qd * 8);
            }
            *(uint4*)(Hhi + r * AST + qd * 8) = vh;
            *(uint4*)(Hlo + r * AST + qd * 8) = vl;
        }
#pragma unroll
        for (int i = 0; i < 4; i++) {
            int u = t + i * 256;
            int r = u >> 4, qd = u & 15;
            float4 w4 = *(const float4*)(Wp + (size_t)r * 256 + kc + qd * 4);
            __nv_bfloat162 h0, l0, h1, l1;
            split2(w4.x, w4.y, h0, l0);
            split2(w4.z, w4.w, h1, l1);
            int so = r * AST + qd * 4;
            *(__nv_bfloat162*)(Phi + so) = h0;  *(__nv_bfloat162*)(Phi + so + 2) = h1;
            *(__nv_bfloat162*)(Plo + so) = l0;  *(__nv_bfloat162*)(Plo + so + 2) = l1;
        }
        __syncthreads();

#pragma unroll
        for (int ks = 0; ks < 4; ks++) {
            uint32_t kbB = ks * 32;
            uint32_t ahi[4], alo[4];
            LDMX4(ahi, aHiB + kbB);
            LDMX4(alo, aLoB + kbB);
#pragma unroll
            for (int ntg = 0; ntg < 4; ntg++) {
                uint32_t cgB = (uint32_t)(ntg * 16 * AST * 2);
                uint32_t bh[4], bl[4];
                LDMX4(bh, bHiB + cgB + kbB);
                LDMX4(bl, bLoB + cgB + kbB);
                mma16816(acc[2 * ntg],     ahi, bh);
                mma16816(acc[2 * ntg + 1], ahi, bh + 2);
                mma16816(acc[2 * ntg],     ahi, bl);
                mma16816(acc[2 * ntg + 1], ahi, bl + 2);
                mma16816(acc[2 * ntg],     alo, bh);
                mma16816(acc[2 * ntg + 1], alo, bh + 2);
            }
        }
    }

    int rA = row0 + r0 + g;
    int rB = rA + 8;
#pragma unroll
    for (int nt = 0; nt < 8; nt++) {
        int lc = nt * 8 + tq * 2;
        float b0 = sbias[lc], b1 = sbias[lc + 1];
        if (rA < NN) {
            float2 xv = *(const float2*)(x + (size_t)rA * 64 + lc);
            *(float2*)(out + (size_t)rA * 64 + lc) =
                make_float2(fmaxf(acc[nt][0] + b0 + xv.x, 0.f), fmaxf(acc[nt][1] + b1 + xv.y, 0.f));
        }
        if (rB < NN) {
            float2 xv = *(const float2*)(x + (size_t)rB * 64 + lc);
            *(float2*)(out + (size_t)rB * 64 + lc) =
                make_float2(fmaxf(acc[nt][2] + b0 + xv.x, 0.f), fmaxf(acc[nt][3] + b1 + xv.y, 0.f));
        }
    }
}

// ============================================================================
extern "C" void kernel_launch(void* const* d_in, const int* in_sizes, int n_in,
                              void* d_out, int out_size)
{
    const float* x     = (const float*)d_in[0];
    const int*   ei    = (const int*)d_in[1];
    const float* Wq    = (const float*)d_in[2];
    const float* bq    = (const float*)d_in[3];
    const float* Wk    = (const float*)d_in[4];
    const float* bk    = (const float*)d_in[5];
    const float* Wv    = (const float*)d_in[6];
    const float* bv    = (const float*)d_in[7];
    const float* Wsk   = (const float*)d_in[8];
    const float* bsk   = (const float*)d_in[9];
    const float* Wbeta = (const float*)d_in[10];
    const float* lng   = (const float*)d_in[11];
    const float* lnb   = (const float*)d_in[12];
    const float* Wp    = (const float*)d_in[13];
    const float* bp    = (const float*)d_in[14];
    float* out = (float*)d_out;

    static int attr_set = 0;
    if (!attr_set) {
        cudaFuncSetAttribute(gemm_qkvs_mma,
                             cudaFuncAttributeMaxDynamicSharedMemorySize, QKV_SMEM_BYTES);
        cudaFuncSetAttribute(gemm_proj_mma,
                             cudaFuncAttributeMaxDynamicSharedMemorySize, PROJ_SMEM_BYTES);
        attr_set = 1;
    }

    hist_kernel<<<2500, 256>>>(ei);
    scan1_kernel<<<NB, 1024>>>();
    scan2_kernel<<<1, 64>>>();
    scan3_kernel<<<NB, 1024>>>();
    scatter_kernel<<<2500, 256>>>(ei);
    gemm_qkvs_mma<<<dim3(8, 391), 256, QKV_SMEM_BYTES>>>(x, Wq, bq, Wk, bk, Wv, bv, Wsk, bsk);
    attn_kernel<<<6250, 256>>>(Wbeta, lng, lnb);
    gemm_proj_mma<<<391, 256, PROJ_SMEM_BYTES>>>(x, Wp, bp, out);
}